// round 16
// baseline (speedup 1.0000x reference)
#include <cuda_runtime.h>
#include <cuda_fp16.h>
#include <cstdint>

#define NN 2048
#define MMT 2048
#define ROWS 14
#define WARPS 28
#define THREADS 896
#define GRID 147
#define HRW 34
#define ASTR 18          // acc/swa per-lane stride (words); 16 used
#define XSTR 12          // packed x_r/rprops row stride (floats), 16B rows

// dynamic smem byte offsets (16B aligned)
#define SO_B4P   0          // uint4[2][8][32]                 8192
#define SO_HRH   8192       // uint32[2][2][544]               8704
#define SO_XRP   16896      // float[2][32*XSTR]               3072
#define SO_BFT   19968      // uint32[32][36] (16 used/lane)   4608
#define SO_ACC   24576      // float[28*32*ASTR]               64512
#define SO_SWA   89088      // float[28*32*ASTR]               64512
#define SO_HSUM  153600     // float[32][68]                   8704
#define SO_SUMH  162304     // float[64]                       256
#define SO_HAGG  162560     // float[14][64]                   3584
#define SO_SSB   166144     // float[14][64]                   3584
#define SO_PART  169728     // float[14][4]                    224
#define SMEM_TOTAL 169952

__device__ __forceinline__ float tanh_ap(float x) {
    float y; asm("tanh.approx.f32 %0, %1;" : "=f"(y) : "f"(x)); return y;
}
__device__ __forceinline__ uint32_t pack_h2(float lo, float hi) {
    uint32_t u; asm("cvt.rn.f16x2.f32 %0, %1, %2;" : "=r"(u) : "f"(hi), "f"(lo)); return u;
}
__device__ __forceinline__ uint32_t h2add(uint32_t a, uint32_t b) {
    uint32_t d; asm("add.rn.f16x2 %0, %1, %2;" : "=r"(d) : "r"(a), "r"(b)); return d;
}
__device__ __forceinline__ uint32_t h2fma(uint32_t a, uint32_t b, uint32_t c) {
    uint32_t d; asm("fma.rn.f16x2 %0, %1, %2, %3;" : "=r"(d) : "r"(a), "r"(b), "r"(c)); return d;
}
__device__ __forceinline__ uint32_t h2tanh(uint32_t a) {
    uint32_t d; asm("tanh.approx.f16x2 %0, %1;" : "=r"(d) : "r"(a)); return d;
}
__device__ __forceinline__ float2 h22f2(uint32_t u) {
    float2 f;
    asm("{ .reg .b16 lo, hi; mov.b32 {lo, hi}, %2; cvt.f32.f16 %0, lo; cvt.f32.f16 %1, hi; }"
        : "=f"(f.x), "=f"(f.y) : "r"(u));
    return f;
}
__device__ __forceinline__ void mma_k8h(uint32_t& d0, uint32_t& d1,
                                        uint32_t a0, uint32_t a1, uint32_t b0) {
    asm volatile(
        "mma.sync.aligned.m16n8k8.row.col.f16.f16.f16.f16 "
        "{%0,%1}, {%2,%3}, {%4}, {%0,%1};"
        : "+r"(d0), "+r"(d1) : "r"(a0), "r"(a1), "r"(b0));
}
__device__ __forceinline__ void mma_k16h(uint32_t& d0, uint32_t& d1,
                                         uint32_t a0, uint32_t a1, uint32_t a2, uint32_t a3,
                                         uint32_t b0, uint32_t b1) {
    asm volatile(
        "mma.sync.aligned.m16n8k16.row.col.f16.f16.f16.f16 "
        "{%0,%1}, {%2,%3,%4,%5}, {%6,%7}, {%0,%1};"
        : "+r"(d0), "+r"(d1)
        : "r"(a0), "r"(a1), "r"(a2), "r"(a3), "r"(b0), "r"(b1));
}
__device__ __forceinline__ int pair_off(int p) {
    return (p & 3) * 8 + ((p >> 3) << 1) + ((p >> 2) & 1);
}
#define PAIR_BAR() asm volatile("bar.sync %0, 64;" :: "r"(1 + wpair) : "memory")

// ---------------------------------------------------------------------------
// R15 structure (best: 187.1us) + R16 deltas:
//  * loop unrolled by 2 with the loop-invariant bft table loads (4x LDS.128)
//    hoisted to once per chunk-pair (values already live through a chunk body;
//    no new peak register pressure).
//  * accH f16x2 flush cadence 4 -> 8 chunks.
// ---------------------------------------------------------------------------
__global__ void __launch_bounds__(THREADS, 1)
fused_kernel(const float* __restrict__ h_l, const float* __restrict__ x_l,
             const float* __restrict__ h_r, const float* __restrict__ x_r,
             const float* __restrict__ W1, const float* __restrict__ b1,
             const float* __restrict__ W2, const float* __restrict__ b2,
             const float* __restrict__ Wn1, const float* __restrict__ bn1,
             const float* __restrict__ ln_g, const float* __restrict__ ln_b,
             const float* __restrict__ Wn2, const float* __restrict__ bn2,
             float* __restrict__ out)
{
    extern __shared__ char smraw[];
    uint4*    b4p   = (uint4*)(smraw + SO_B4P);
    uint32_t* hrh   = (uint32_t*)(smraw + SO_HRH);
    float*    xrp   = (float*)(smraw + SO_XRP);
    uint32_t* bft   = (uint32_t*)(smraw + SO_BFT);
    float*    accS  = (float*)(smraw + SO_ACC);
    float*    swaS  = (float*)(smraw + SO_SWA);
    float (*hsum_s)[68] = (float(*)[68])(smraw + SO_HSUM);
    float*    sumH_s = (float*)(smraw + SO_SUMH);
    float (*hagg_s)[64] = (float(*)[64])(smraw + SO_HAGG);
    float (*ssb)[64]    = (float(*)[64])(smraw + SO_SSB);
    float*    part  = (float*)(smraw + SO_PART);

    const int tid   = threadIdx.x;
    const int w     = tid >> 5;
    const int lane  = tid & 31;
    const int wpair = w >> 1;
    const int half  = w & 1;
    const int r     = lane >> 2;
    const int q     = lane & 3;

    // ---- one-time: 0.5*W2 fragments, lane-indexed ----
    for (int i = tid; i < 512; i += THREADS) {
        int l  = i & 31, nt = (i >> 5) & 7, kp = i >> 8;
        int rr = l >> 2, qq = l & 3;
        int c  = nt * 8 + rr;
        uint4 v;
        {
            int j0 = (2 * kp) * 16 + 2 * qq;
            v.x = pack_h2(0.5f * W2[j0 * 64 + c],       0.5f * W2[(j0 + 1) * 64 + c]);
            v.y = pack_h2(0.5f * W2[(j0 + 8) * 64 + c], 0.5f * W2[(j0 + 9) * 64 + c]);
        }
        {
            int j0 = (2 * kp + 1) * 16 + 2 * qq;
            v.z = pack_h2(0.5f * W2[j0 * 64 + c],       0.5f * W2[(j0 + 1) * 64 + c]);
            v.w = pack_h2(0.5f * W2[(j0 + 8) * 64 + c], 0.5f * W2[(j0 + 9) * 64 + c]);
        }
        b4p[(kp * 8 + nt) * 32 + l] = v;
    }
    // ---- one-time: per-lane table (0.5*W1 frags + 0.5*b2) ----
    for (int i = tid; i < 512; i += THREADS) {
        int l = i >> 4, word = i & 15;
        int rr = l >> 2, qq = l & 3;
        uint32_t v;
        if (word < 8) {
            int cc = word * 8 + rr;
            v = (qq == 0) ? pack_h2(0.5f * W1[cc], 0.5f * W1[64 + cc])
              : (qq == 1) ? pack_h2(0.5f * W1[128 + cc], 0.5f * (W1[192 + cc] + b1[cc]))
              : 0u;
        } else {
            int c0 = (word - 8) * 8 + 2 * qq;
            v = pack_h2(0.5f * b2[c0], 0.5f * b2[c0 + 1]);
        }
        bft[l * 36 + word] = v;
    }

    int nrow = blockIdx.x * ROWS + wpair;
    if (nrow > NN - 1) nrow = NN - 1;
    const float xlx = x_l[nrow * 3 + 0];
    const float xly = x_l[nrow * 3 + 1];
    const float xlz = x_l[nrow * 3 + 2];
    const float l0  = h_l[nrow * 64 + 61];
    const float l1  = h_l[nrow * 64 + 62];
    const float l2  = h_l[nrow * 64 + 63];

    const int mi0 = r, mi1 = r + 8;

    uint32_t accH[8], sswa[8];
    #pragma unroll
    for (int i = 0; i < 8; i++) { accH[i] = 0u; sswa[i] = 0u; }

    float* accp  = accS + (w * 32 + lane) * ASTR;
    float* swap_ = swaS + (w * 32 + lane) * ASTR;
    #pragma unroll
    for (int j = 0; j < 16; j += 2) {
        *(float2*)(accp + j)  = make_float2(0.f, 0.f);
        *(float2*)(swap_ + j) = make_float2(0.f, 0.f);
    }

    const uint32_t* bfl = bft + lane * 36;

    // hoisted per-buffer bases
    const float* xp_b0 = xrp + half * 16 * XSTR;
    const float* xp_b1 = xrp + 384 + half * 16 * XSTR;
    const uint32_t* hb_b0 = hrh + half * 544;
    const uint32_t* hb_b1 = hrh + (2 + half) * 544;

    const int mm_ld = tid >> 4, k_ld = tid & 15;
    const int sub_ld = mm_ld >> 4, row_ld = mm_ld & 15;
    const int off0 = pair_off(2 * k_ld);
    const int off1 = pair_off(2 * k_ld + 1);
    float4 hsum = make_float4(0.f, 0.f, 0.f, 0.f);

    #define LOAD_SUPER(m0_, sb_) do {                                           \
        if (tid < 96)                                                           \
            xrp[(sb_) * 384 + (tid / 3) * XSTR + tid % 3] = x_r[(m0_) * 3 + tid]; \
        else if (tid >= 128 && tid < 224) {                                     \
            int t = tid - 128;                                                  \
            xrp[(sb_) * 384 + (t / 3) * XSTR + 3 + t % 3] =                     \
                h_r[((m0_) + t / 3) * 64 + 61 + t % 3];                         \
        }                                                                       \
        if (tid < 512) {                                                        \
            float4 v = ((const float4*)(h_r + (m0_) * 64))[tid];                \
            hsum.x += v.x; hsum.y += v.y; hsum.z += v.z; hsum.w += v.w;         \
            uint32_t* dst = hrh + ((sb_) * 2 + sub_ld) * 544 + row_ld * HRW;    \
            dst[off0] = pack_h2(v.x, v.y);                                      \
            dst[off1] = pack_h2(v.z, v.w);                                      \
        }                                                                       \
    } while (0)

    // one full 32-m chunk; bf0..hb1 must be in scope (loaded once per pair)
    #define CHUNK_BODY(sc_) do {                                                \
        const int buf = (sc_) & 1;                                              \
        __syncthreads();                                                        \
        if ((sc_) + 1 < 64) LOAD_SUPER(((sc_) + 1) * 32, buf ^ 1);              \
        const float* xp = buf ? xp_b1 : xp_b0;                                  \
        const uint32_t* hb = buf ? hb_b1 : hb_b0;                               \
        float4 v0 = *(const float4*)(xp + mi0 * XSTR);                          \
        float2 u0 = *(const float2*)(xp + mi0 * XSTR + 4);                      \
        float4 v1 = *(const float4*)(xp + mi1 * XSTR);                          \
        float2 u1 = *(const float2*)(xp + mi1 * XSTR + 4);                      \
        float dx = xlx - v0.x, dy = xly - v0.y, dz = xlz - v0.z;                \
        float d2 = fmaf(dx, dx, fmaf(dy, dy, dz * dz));                         \
        float a0v = __expf(-0.2f * d2);                                         \
        float bh0 = fmaf(l0, u0.x, l1 * v0.w);                                  \
        float ch0 = l2 * u0.y;                                                  \
        dx = xlx - v1.x; dy = xly - v1.y; dz = xlz - v1.z;                      \
        d2 = fmaf(dx, dx, fmaf(dy, dy, dz * dz));                               \
        float a1v = __expf(-0.2f * d2);                                         \
        float bh1 = fmaf(l0, u1.x, l1 * v1.w);                                  \
        float ch1 = l2 * u1.y;                                                  \
        float e00 = (q == 0) ? a0v : (q == 1) ? ch0 : 0.f;                      \
        float e01 = (q == 0) ? bh0 : (q == 1) ? 1.f : 0.f;                      \
        float e10 = (q == 0) ? a1v : (q == 1) ? ch1 : 0.f;                      \
        float e11 = (q == 0) ? bh1 : (q == 1) ? 1.f : 0.f;                      \
        uint32_t A10 = pack_h2(e00, e01);                                       \
        uint32_t A11 = pack_h2(e10, e11);                                       \
        uint32_t A2[4][4];                                                      \
        {                                                                       \
            uint32_t bb[8] = {bf0.x, bf0.y, bf0.z, bf0.w,                       \
                              bf1.x, bf1.y, bf1.z, bf1.w};                      \
            _Pragma("unroll")                                                   \
            for (int kt = 0; kt < 4; kt++) {                                    \
                uint32_t p00 = 0u, p01 = 0u, p10 = 0u, p11 = 0u;                \
                mma_k8h(p00, p01, A10, A11, bb[2 * kt]);                        \
                mma_k8h(p10, p11, A10, A11, bb[2 * kt + 1]);                    \
                A2[kt][0] = h2fma(p00, h2tanh(p00), p00);                       \
                A2[kt][1] = h2fma(p01, h2tanh(p01), p01);                       \
                A2[kt][2] = h2fma(p10, h2tanh(p10), p10);                       \
                A2[kt][3] = h2fma(p11, h2tanh(p11), p11);                       \
            }                                                                   \
        }                                                                       \
        const uint32_t* hp0 = hb + mi0 * HRW + q * 8;                           \
        const uint32_t* hp1 = hb + mi1 * HRW + q * 8;                           \
        {                                                                       \
            uint32_t hbv[8] = {hb0.x, hb0.y, hb0.z, hb0.w,                      \
                               hb1.x, hb1.y, hb1.z, hb1.w};                     \
            _Pragma("unroll")                                                   \
            for (int np = 0; np < 4; np++) {                                    \
                uint2 H0 = *(const uint2*)(hp0 + np * 2);                       \
                uint2 H1 = *(const uint2*)(hp1 + np * 2);                       \
                _Pragma("unroll")                                               \
                for (int s = 0; s < 2; s++) {                                   \
                    const int nt = np * 2 + s;                                  \
                    uint32_t D01 = hbv[nt], D23 = hbv[nt];                      \
                    uint4 B0 = b4p[nt * 32 + lane];                             \
                    uint4 B1 = b4p[(8 + nt) * 32 + lane];                       \
                    mma_k16h(D01, D23, A2[0][0], A2[0][1], A2[0][2], A2[0][3], B0.x, B0.y); \
                    mma_k16h(D01, D23, A2[1][0], A2[1][1], A2[1][2], A2[1][3], B0.z, B0.w); \
                    mma_k16h(D01, D23, A2[2][0], A2[2][1], A2[2][2], A2[2][3], B1.x, B1.y); \
                    mma_k16h(D01, D23, A2[3][0], A2[3][1], A2[3][2], A2[3][3], B1.z, B1.w); \
                    uint32_t t01 = h2tanh(D01);                                 \
                    uint32_t t23 = h2tanh(D23);                                 \
                    uint32_t h0 = s ? H0.y : H0.x;                              \
                    uint32_t h1 = s ? H1.y : H1.x;                              \
                    accH[nt] = h2fma(t01, h0, accH[nt]);                        \
                    accH[nt] = h2fma(t23, h1, accH[nt]);                        \
                    sswa[nt] = h2add(sswa[nt], h2add(t01, t23));                \
                }                                                               \
            }                                                                   \
        }                                                                       \
        if (((sc_) & 7) == 7) {                                                 \
            _Pragma("unroll")                                                   \
            for (int nt = 0; nt < 8; nt++) {                                    \
                float2 v = *(float2*)(accp + 2 * nt);                           \
                float2 a = h22f2(accH[nt]);                                     \
                v.x += a.x; v.y += a.y;                                         \
                *(float2*)(accp + 2 * nt) = v;                                  \
                accH[nt] = 0u;                                                  \
            }                                                                   \
        }                                                                       \
        if (((sc_) & 15) == 15) {                                               \
            _Pragma("unroll")                                                   \
            for (int nt = 0; nt < 8; nt++) {                                    \
                float2 v = *(float2*)(swap_ + 2 * nt);                          \
                float2 s2 = h22f2(sswa[nt]);                                    \
                v.x += s2.x; v.y += s2.y;                                       \
                *(float2*)(swap_ + 2 * nt) = v;                                 \
                sswa[nt] = 0u;                                                  \
            }                                                                   \
        }                                                                       \
    } while (0)

    LOAD_SUPER(0, 0);

    for (int scp = 0; scp < 32; scp++) {
        // loop-invariant table loads once per chunk PAIR
        uint4 bf0 = *(const uint4*)(bfl);
        uint4 bf1 = *(const uint4*)(bfl + 4);
        uint4 hb0 = *(const uint4*)(bfl + 8);
        uint4 hb1 = *(const uint4*)(bfl + 12);

        CHUNK_BODY(2 * scp);
        CHUNK_BODY(2 * scp + 1);
    }

    __syncthreads();
    if (tid < 512) *(float4*)&hsum_s[mm_ld][4 * k_ld] = hsum;
    __syncthreads();
    if (tid < 64) {
        float s = 0.f;
        #pragma unroll
        for (int m = 0; m < 32; m++) s += hsum_s[m][tid];
        sumH_s[tid] = s;
    }
    __syncthreads();

    if (half == 0) {
        float* pacc = accS + ((w + 1) * 32 + lane) * ASTR;
        float* pswa = swaS + ((w + 1) * 32 + lane) * ASTR;
        float accF[16], swaf[16];
        #pragma unroll
        for (int j = 0; j < 16; j += 2) {
            float2 a = *(float2*)(accp + j);
            float2 b = *(float2*)(pacc + j);
            accF[j] = a.x + b.x; accF[j + 1] = a.y + b.y;
            float2 c = *(float2*)(swap_ + j);
            float2 d = *(float2*)(pswa + j);
            swaf[j] = c.x + d.x; swaf[j + 1] = c.y + d.y;
        }
        #pragma unroll
        for (int j = 0; j < 16; j++) {
            #pragma unroll
            for (int off = 4; off <= 16; off <<= 1) {
                accF[j] += __shfl_xor_sync(0xffffffffu, accF[j], off);
                swaf[j] += __shfl_xor_sync(0xffffffffu, swaf[j], off);
            }
        }
        if (lane < 4) {
            #pragma unroll
            for (int nt = 0; nt < 8; nt++) {
                int c0 = nt * 8 + 2 * lane;
                float num0 = fmaf(0.5f, accF[2 * nt],     0.5f * sumH_s[c0]);
                float num1 = fmaf(0.5f, accF[2 * nt + 1], 0.5f * sumH_s[c0 + 1]);
                float den0 = fmaf(0.5f, swaf[2 * nt],     1024.0f + 1e-6f);
                float den1 = fmaf(0.5f, swaf[2 * nt + 1], 1024.0f + 1e-6f);
                hagg_s[wpair][c0]     = num0 / den0;
                hagg_s[wpair][c0 + 1] = num1 / den1;
            }
        }
    }
    __syncthreads();

    {
        const int c = 32 * half + lane;
        float z = bn1[c];
        #pragma unroll 8
        for (int i = 0; i < 64; i++)
            z = fmaf(h_l[nrow * 64 + i], Wn1[i * 64 + c], z);
        #pragma unroll 8
        for (int i = 0; i < 64; i++)
            z = fmaf(hagg_s[wpair][i], Wn1[(64 + i) * 64 + c], z);

        float s = z;
        #pragma unroll
        for (int off = 16; off >= 1; off >>= 1) s += __shfl_xor_sync(0xffffffffu, s, off);
        if (lane == 0) part[wpair * 4 + half] = s;
        PAIR_BAR();
        float mu = (part[wpair * 4] + part[wpair * 4 + 1]) * (1.0f / 64.0f);
        float d = z - mu;
        float v = d * d;
        #pragma unroll
        for (int off = 16; off >= 1; off >>= 1) v += __shfl_xor_sync(0xffffffffu, v, off);
        if (lane == 0) part[wpair * 4 + 2 + half] = v;
        PAIR_BAR();
        float var = (part[wpair * 4 + 2] + part[wpair * 4 + 3]) * (1.0f / 64.0f);
        float rstd = rsqrtf(var + 1e-5f);

        float zn = fmaf(d * rstd, ln_g[c], ln_b[c]);
        float hp = 0.5f * zn;
        ssb[wpair][c] = fmaf(hp, tanh_ap(hp), hp);
        PAIR_BAR();

        float o = bn2[c];
        #pragma unroll 8
        for (int i = 0; i < 64; i++)
            o = fmaf(ssb[wpair][i], Wn2[i * 64 + c], o);
        out[nrow * 64 + c] = h_l[nrow * 64 + c] + o;
    }
}

extern "C" void kernel_launch(void* const* d_in, const int* in_sizes, int n_in,
                              void* d_out, int out_size)
{
    const float* h_l  = (const float*)d_in[0];
    const float* x_l  = (const float*)d_in[1];
    const float* h_r  = (const float*)d_in[2];
    const float* x_r  = (const float*)d_in[3];
    const float* W1   = (const float*)d_in[4];
    const float* b1   = (const float*)d_in[5];
    const float* W2   = (const float*)d_in[6];
    const float* b2   = (const float*)d_in[7];
    const float* Wn1  = (const float*)d_in[8];
    const float* bn1  = (const float*)d_in[9];
    const float* ln_g = (const float*)d_in[10];
    const float* ln_b = (const float*)d_in[11];
    const float* Wn2  = (const float*)d_in[12];
    const float* bn2  = (const float*)d_in[13];
    float* out = (float*)d_out;

    cudaFuncSetAttribute(fused_kernel,
                         cudaFuncAttributeMaxDynamicSharedMemorySize, SMEM_TOTAL);
    fused_kernel<<<GRID, THREADS, SMEM_TOTAL>>>(h_l, x_l, h_r, x_r, W1, b1, W2, b2,
                                                Wn1, bn1, ln_g, ln_b, Wn2, bn2, out);
}

// round 17
// speedup vs baseline: 1.1685x; 1.1685x over previous
#include <cuda_runtime.h>
#include <cuda_fp16.h>
#include <cstdint>

#define NN 2048
#define MMT 2048
#define ROWS 14
#define WARPS 28
#define THREADS 896
#define GRID 147
#define HRW 34
#define ASTR 18          // acc/swa per-lane stride (words); 16 used
#define XSTR 12          // packed x_r/rprops row stride (floats), 16B rows

// dynamic smem byte offsets (16B aligned)
#define SO_B4P   0          // uint4[2][8][32]                 8192
#define SO_HRH   8192       // uint32[2][2][544]               8704
#define SO_XRP   16896      // float[2][32*XSTR]               3072
#define SO_BFT   19968      // uint32[32][36] (16 used/lane)   4608
#define SO_ACC   24576      // float[28*32*ASTR]               64512
#define SO_SWA   89088      // float[28*32*ASTR]               64512
#define SO_HSUM  153600     // float[32][68]                   8704
#define SO_SUMH  162304     // float[64]                       256
#define SO_HAGG  162560     // float[14][64]                   3584
#define SO_SSB   166144     // float[14][64]                   3584
#define SO_PART  169728     // float[14][4]                    224
#define SMEM_TOTAL 169952

__device__ __forceinline__ float tanh_ap(float x) {
    float y; asm("tanh.approx.f32 %0, %1;" : "=f"(y) : "f"(x)); return y;
}
__device__ __forceinline__ uint32_t pack_h2(float lo, float hi) {
    uint32_t u; asm("cvt.rn.f16x2.f32 %0, %1, %2;" : "=r"(u) : "f"(hi), "f"(lo)); return u;
}
__device__ __forceinline__ uint32_t h2add(uint32_t a, uint32_t b) {
    uint32_t d; asm("add.rn.f16x2 %0, %1, %2;" : "=r"(d) : "r"(a), "r"(b)); return d;
}
__device__ __forceinline__ uint32_t h2fma(uint32_t a, uint32_t b, uint32_t c) {
    uint32_t d; asm("fma.rn.f16x2 %0, %1, %2, %3;" : "=r"(d) : "r"(a), "r"(b), "r"(c)); return d;
}
__device__ __forceinline__ uint32_t h2tanh(uint32_t a) {
    uint32_t d; asm("tanh.approx.f16x2 %0, %1;" : "=r"(d) : "r"(a)); return d;
}
__device__ __forceinline__ float2 h22f2(uint32_t u) {
    float2 f;
    asm("{ .reg .b16 lo, hi; mov.b32 {lo, hi}, %2; cvt.f32.f16 %0, lo; cvt.f32.f16 %1, hi; }"
        : "=f"(f.x), "=f"(f.y) : "r"(u));
    return f;
}
__device__ __forceinline__ void mma_k8h(uint32_t& d0, uint32_t& d1,
                                        uint32_t a0, uint32_t a1, uint32_t b0) {
    asm volatile(
        "mma.sync.aligned.m16n8k8.row.col.f16.f16.f16.f16 "
        "{%0,%1}, {%2,%3}, {%4}, {%0,%1};"
        : "+r"(d0), "+r"(d1) : "r"(a0), "r"(a1), "r"(b0));
}
__device__ __forceinline__ void mma_k16h(uint32_t& d0, uint32_t& d1,
                                         uint32_t a0, uint32_t a1, uint32_t a2, uint32_t a3,
                                         uint32_t b0, uint32_t b1) {
    asm volatile(
        "mma.sync.aligned.m16n8k16.row.col.f16.f16.f16.f16 "
        "{%0,%1}, {%2,%3,%4,%5}, {%6,%7}, {%0,%1};"
        : "+r"(d0), "+r"(d1)
        : "r"(a0), "r"(a1), "r"(a2), "r"(a3), "r"(b0), "r"(b1));
}
__device__ __forceinline__ int pair_off(int p) {
    return (p & 3) * 8 + ((p >> 3) << 1) + ((p >> 2) & 1);
}
#define PAIR_BAR() asm volatile("bar.sync %0, 64;" :: "r"(1 + wpair) : "memory")

// ---------------------------------------------------------------------------
// Verified optimum (R15, 187.1us): m-split, 2 warps per node row; warp half h
// processes sub-chunk h of each 32-m superchunk; full f16-MMA pipeline per
// warp (MMA1 edge-raw@W1 -> f16x2 silu -> MMA2 hidden@W2 bias-init -> f16x2
// tanh -> f16x2 accumulate, fp32 flush cadence 4/16); stage-1 inputs packed
// [m][12]; per-lane weight tables; bft loads hoisted per chunk (NOT across
// chunks - spills); merge once at the end; node MLP fused tail.
// ---------------------------------------------------------------------------
__global__ void __launch_bounds__(THREADS, 1)
fused_kernel(const float* __restrict__ h_l, const float* __restrict__ x_l,
             const float* __restrict__ h_r, const float* __restrict__ x_r,
             const float* __restrict__ W1, const float* __restrict__ b1,
             const float* __restrict__ W2, const float* __restrict__ b2,
             const float* __restrict__ Wn1, const float* __restrict__ bn1,
             const float* __restrict__ ln_g, const float* __restrict__ ln_b,
             const float* __restrict__ Wn2, const float* __restrict__ bn2,
             float* __restrict__ out)
{
    extern __shared__ char smraw[];
    uint4*    b4p   = (uint4*)(smraw + SO_B4P);
    uint32_t* hrh   = (uint32_t*)(smraw + SO_HRH);
    float*    xrp   = (float*)(smraw + SO_XRP);
    uint32_t* bft   = (uint32_t*)(smraw + SO_BFT);
    float*    accS  = (float*)(smraw + SO_ACC);
    float*    swaS  = (float*)(smraw + SO_SWA);
    float (*hsum_s)[68] = (float(*)[68])(smraw + SO_HSUM);
    float*    sumH_s = (float*)(smraw + SO_SUMH);
    float (*hagg_s)[64] = (float(*)[64])(smraw + SO_HAGG);
    float (*ssb)[64]    = (float(*)[64])(smraw + SO_SSB);
    float*    part  = (float*)(smraw + SO_PART);

    const int tid   = threadIdx.x;
    const int w     = tid >> 5;
    const int lane  = tid & 31;
    const int wpair = w >> 1;
    const int half  = w & 1;
    const int r     = lane >> 2;
    const int q     = lane & 3;

    // ---- one-time: 0.5*W2 fragments, lane-indexed ----
    for (int i = tid; i < 512; i += THREADS) {
        int l  = i & 31, nt = (i >> 5) & 7, kp = i >> 8;
        int rr = l >> 2, qq = l & 3;
        int c  = nt * 8 + rr;
        uint4 v;
        {
            int j0 = (2 * kp) * 16 + 2 * qq;
            v.x = pack_h2(0.5f * W2[j0 * 64 + c],       0.5f * W2[(j0 + 1) * 64 + c]);
            v.y = pack_h2(0.5f * W2[(j0 + 8) * 64 + c], 0.5f * W2[(j0 + 9) * 64 + c]);
        }
        {
            int j0 = (2 * kp + 1) * 16 + 2 * qq;
            v.z = pack_h2(0.5f * W2[j0 * 64 + c],       0.5f * W2[(j0 + 1) * 64 + c]);
            v.w = pack_h2(0.5f * W2[(j0 + 8) * 64 + c], 0.5f * W2[(j0 + 9) * 64 + c]);
        }
        b4p[(kp * 8 + nt) * 32 + l] = v;
    }
    // ---- one-time: per-lane table (0.5*W1 frags + 0.5*b2) ----
    for (int i = tid; i < 512; i += THREADS) {
        int l = i >> 4, word = i & 15;
        int rr = l >> 2, qq = l & 3;
        uint32_t v;
        if (word < 8) {
            int cc = word * 8 + rr;
            v = (qq == 0) ? pack_h2(0.5f * W1[cc], 0.5f * W1[64 + cc])
              : (qq == 1) ? pack_h2(0.5f * W1[128 + cc], 0.5f * (W1[192 + cc] + b1[cc]))
              : 0u;
        } else {
            int c0 = (word - 8) * 8 + 2 * qq;
            v = pack_h2(0.5f * b2[c0], 0.5f * b2[c0 + 1]);
        }
        bft[l * 36 + word] = v;
    }

    int nrow = blockIdx.x * ROWS + wpair;
    if (nrow > NN - 1) nrow = NN - 1;
    const float xlx = x_l[nrow * 3 + 0];
    const float xly = x_l[nrow * 3 + 1];
    const float xlz = x_l[nrow * 3 + 2];
    const float l0  = h_l[nrow * 64 + 61];
    const float l1  = h_l[nrow * 64 + 62];
    const float l2  = h_l[nrow * 64 + 63];

    const int mi0 = r, mi1 = r + 8;

    uint32_t accH[8], sswa[8];
    #pragma unroll
    for (int i = 0; i < 8; i++) { accH[i] = 0u; sswa[i] = 0u; }

    float* accp  = accS + (w * 32 + lane) * ASTR;
    float* swap_ = swaS + (w * 32 + lane) * ASTR;
    #pragma unroll
    for (int j = 0; j < 16; j += 2) {
        *(float2*)(accp + j)  = make_float2(0.f, 0.f);
        *(float2*)(swap_ + j) = make_float2(0.f, 0.f);
    }

    const uint32_t* bfl = bft + lane * 36;

    // hoisted per-buffer bases (warp view of packed rows / hrh sub-buffer)
    const float* xp_b0 = xrp + half * 16 * XSTR;
    const float* xp_b1 = xrp + 384 + half * 16 * XSTR;
    const uint32_t* hb_b0 = hrh + half * 544;
    const uint32_t* hb_b1 = hrh + (2 + half) * 544;

    const int mm_ld = tid >> 4, k_ld = tid & 15;
    const int sub_ld = mm_ld >> 4, row_ld = mm_ld & 15;
    const int off0 = pair_off(2 * k_ld);
    const int off1 = pair_off(2 * k_ld + 1);
    float4 hsum = make_float4(0.f, 0.f, 0.f, 0.f);

    #define LOAD_SUPER(m0_, sb_) do {                                           \
        if (tid < 96)                                                           \
            xrp[(sb_) * 384 + (tid / 3) * XSTR + tid % 3] = x_r[(m0_) * 3 + tid]; \
        else if (tid >= 128 && tid < 224) {                                     \
            int t = tid - 128;                                                  \
            xrp[(sb_) * 384 + (t / 3) * XSTR + 3 + t % 3] =                     \
                h_r[((m0_) + t / 3) * 64 + 61 + t % 3];                         \
        }                                                                       \
        if (tid < 512) {                                                        \
            float4 v = ((const float4*)(h_r + (m0_) * 64))[tid];                \
            hsum.x += v.x; hsum.y += v.y; hsum.z += v.z; hsum.w += v.w;         \
            uint32_t* dst = hrh + ((sb_) * 2 + sub_ld) * 544 + row_ld * HRW;    \
            dst[off0] = pack_h2(v.x, v.y);                                      \
            dst[off1] = pack_h2(v.z, v.w);                                      \
        }                                                                       \
    } while (0)

    LOAD_SUPER(0, 0);

    for (int sc = 0; sc < 64; sc++) {
        const int buf = sc & 1;
        __syncthreads();
        if (sc + 1 < 64) LOAD_SUPER((sc + 1) * 32, buf ^ 1);

        // ---- loop-invariant table loads FIRST (overlap with stage-1 chain) ----
        uint4 bf0 = *(const uint4*)(bfl);
        uint4 bf1 = *(const uint4*)(bfl + 4);
        uint4 hb0 = *(const uint4*)(bfl + 8);
        uint4 hb1 = *(const uint4*)(bfl + 12);

        const float* xp = buf ? xp_b1 : xp_b0;
        const uint32_t* hb = buf ? hb_b1 : hb_b0;

        // ---- stage 1: packed reads {x,y,z,rp0} + {rp1,rp2} per m-row ----
        float4 v0 = *(const float4*)(xp + mi0 * XSTR);
        float2 u0 = *(const float2*)(xp + mi0 * XSTR + 4);
        float4 v1 = *(const float4*)(xp + mi1 * XSTR);
        float2 u1 = *(const float2*)(xp + mi1 * XSTR + 4);

        float dx = xlx - v0.x, dy = xly - v0.y, dz = xlz - v0.z;
        float d2 = fmaf(dx, dx, fmaf(dy, dy, dz * dz));
        float a0v = __expf(-0.2f * d2);
        float bh0 = fmaf(l0, u0.x, l1 * v0.w);
        float ch0 = l2 * u0.y;

        dx = xlx - v1.x; dy = xly - v1.y; dz = xlz - v1.z;
        d2 = fmaf(dx, dx, fmaf(dy, dy, dz * dz));
        float a1v = __expf(-0.2f * d2);
        float bh1 = fmaf(l0, u1.x, l1 * v1.w);
        float ch1 = l2 * u1.y;

        float e00 = (q == 0) ? a0v : (q == 1) ? ch0 : 0.f;
        float e01 = (q == 0) ? bh0 : (q == 1) ? 1.f : 0.f;
        float e10 = (q == 0) ? a1v : (q == 1) ? ch1 : 0.f;
        float e11 = (q == 0) ? bh1 : (q == 1) ? 1.f : 0.f;
        uint32_t A10 = pack_h2(e00, e01);
        uint32_t A11 = pack_h2(e10, e11);

        // ---- MMA1 (0.5-scaled) + silu -> A2 ----
        uint32_t A2[4][4];
        {
            uint32_t bb[8] = {bf0.x, bf0.y, bf0.z, bf0.w, bf1.x, bf1.y, bf1.z, bf1.w};
            #pragma unroll
            for (int kt = 0; kt < 4; kt++) {
                uint32_t p00 = 0u, p01 = 0u, p10 = 0u, p11 = 0u;
                mma_k8h(p00, p01, A10, A11, bb[2 * kt]);
                mma_k8h(p10, p11, A10, A11, bb[2 * kt + 1]);
                A2[kt][0] = h2fma(p00, h2tanh(p00), p00);
                A2[kt][1] = h2fma(p01, h2tanh(p01), p01);
                A2[kt][2] = h2fma(p10, h2tanh(p10), p10);
                A2[kt][3] = h2fma(p11, h2tanh(p11), p11);
            }
        }

        // ---- MMA2 with bias-initialized accumulator + tanh + accumulate ----
        const uint32_t* hp0 = hb + mi0 * HRW + q * 8;
        const uint32_t* hp1 = hb + mi1 * HRW + q * 8;
        {
            uint32_t hbv[8] = {hb0.x, hb0.y, hb0.z, hb0.w, hb1.x, hb1.y, hb1.z, hb1.w};
            #pragma unroll
            for (int np = 0; np < 4; np++) {
                uint2 H0 = *(const uint2*)(hp0 + np * 2);
                uint2 H1 = *(const uint2*)(hp1 + np * 2);
                #pragma unroll
                for (int s = 0; s < 2; s++) {
                    const int nt = np * 2 + s;
                    uint32_t D01 = hbv[nt], D23 = hbv[nt];
                    uint4 B0 = b4p[nt * 32 + lane];
                    uint4 B1 = b4p[(8 + nt) * 32 + lane];
                    mma_k16h(D01, D23, A2[0][0], A2[0][1], A2[0][2], A2[0][3], B0.x, B0.y);
                    mma_k16h(D01, D23, A2[1][0], A2[1][1], A2[1][2], A2[1][3], B0.z, B0.w);
                    mma_k16h(D01, D23, A2[2][0], A2[2][1], A2[2][2], A2[2][3], B1.x, B1.y);
                    mma_k16h(D01, D23, A2[3][0], A2[3][1], A2[3][2], A2[3][3], B1.z, B1.w);

                    uint32_t t01 = h2tanh(D01);
                    uint32_t t23 = h2tanh(D23);
                    uint32_t h0 = s ? H0.y : H0.x;
                    uint32_t h1 = s ? H1.y : H1.x;
                    accH[nt] = h2fma(t01, h0, accH[nt]);
                    accH[nt] = h2fma(t23, h1, accH[nt]);
                    sswa[nt] = h2add(sswa[nt], h2add(t01, t23));
                }
            }
        }

        if ((sc & 3) == 3) {
            #pragma unroll
            for (int nt = 0; nt < 8; nt++) {
                float2 v = *(float2*)(accp + 2 * nt);
                float2 a = h22f2(accH[nt]);
                v.x += a.x; v.y += a.y;
                *(float2*)(accp + 2 * nt) = v;
                accH[nt] = 0u;
            }
        }
        if ((sc & 15) == 15) {
            #pragma unroll
            for (int nt = 0; nt < 8; nt++) {
                float2 v = *(float2*)(swap_ + 2 * nt);
                float2 s2 = h22f2(sswa[nt]);
                v.x += s2.x; v.y += s2.y;
                *(float2*)(swap_ + 2 * nt) = v;
                sswa[nt] = 0u;
            }
        }
    }

    __syncthreads();
    if (tid < 512) *(float4*)&hsum_s[mm_ld][4 * k_ld] = hsum;
    __syncthreads();
    if (tid < 64) {
        float s = 0.f;
        #pragma unroll
        for (int m = 0; m < 32; m++) s += hsum_s[m][tid];
        sumH_s[tid] = s;
    }
    __syncthreads();

    if (half == 0) {
        float* pacc = accS + ((w + 1) * 32 + lane) * ASTR;
        float* pswa = swaS + ((w + 1) * 32 + lane) * ASTR;
        float accF[16], swaf[16];
        #pragma unroll
        for (int j = 0; j < 16; j += 2) {
            float2 a = *(float2*)(accp + j);
            float2 b = *(float2*)(pacc + j);
            accF[j] = a.x + b.x; accF[j + 1] = a.y + b.y;
            float2 c = *(float2*)(swap_ + j);
            float2 d = *(float2*)(pswa + j);
            swaf[j] = c.x + d.x; swaf[j + 1] = c.y + d.y;
        }
        #pragma unroll
        for (int j = 0; j < 16; j++) {
            #pragma unroll
            for (int off = 4; off <= 16; off <<= 1) {
                accF[j] += __shfl_xor_sync(0xffffffffu, accF[j], off);
                swaf[j] += __shfl_xor_sync(0xffffffffu, swaf[j], off);
            }
        }
        if (lane < 4) {
            #pragma unroll
            for (int nt = 0; nt < 8; nt++) {
                int c0 = nt * 8 + 2 * lane;
                float num0 = fmaf(0.5f, accF[2 * nt],     0.5f * sumH_s[c0]);
                float num1 = fmaf(0.5f, accF[2 * nt + 1], 0.5f * sumH_s[c0 + 1]);
                float den0 = fmaf(0.5f, swaf[2 * nt],     1024.0f + 1e-6f);
                float den1 = fmaf(0.5f, swaf[2 * nt + 1], 1024.0f + 1e-6f);
                hagg_s[wpair][c0]     = num0 / den0;
                hagg_s[wpair][c0 + 1] = num1 / den1;
            }
        }
    }
    __syncthreads();

    {
        const int c = 32 * half + lane;
        float z = bn1[c];
        #pragma unroll 8
        for (int i = 0; i < 64; i++)
            z = fmaf(h_l[nrow * 64 + i], Wn1[i * 64 + c], z);
        #pragma unroll 8
        for (int i = 0; i < 64; i++)
            z = fmaf(hagg_s[wpair][i], Wn1[(64 + i) * 64 + c], z);

        float s = z;
        #pragma unroll
        for (int off = 16; off >= 1; off >>= 1) s += __shfl_xor_sync(0xffffffffu, s, off);
        if (lane == 0) part[wpair * 4 + half] = s;
        PAIR_BAR();
        float mu = (part[wpair * 4] + part[wpair * 4 + 1]) * (1.0f / 64.0f);
        float d = z - mu;
        float v = d * d;
        #pragma unroll
        for (int off = 16; off >= 1; off >>= 1) v += __shfl_xor_sync(0xffffffffu, v, off);
        if (lane == 0) part[wpair * 4 + 2 + half] = v;
        PAIR_BAR();
        float var = (part[wpair * 4 + 2] + part[wpair * 4 + 3]) * (1.0f / 64.0f);
        float rstd = rsqrtf(var + 1e-5f);

        float zn = fmaf(d * rstd, ln_g[c], ln_b[c]);
        float hp = 0.5f * zn;
        ssb[wpair][c] = fmaf(hp, tanh_ap(hp), hp);
        PAIR_BAR();

        float o = bn2[c];
        #pragma unroll 8
        for (int i = 0; i < 64; i++)
            o = fmaf(ssb[wpair][i], Wn2[i * 64 + c], o);
        out[nrow * 64 + c] = h_l[nrow * 64 + c] + o;
    }
}

extern "C" void kernel_launch(void* const* d_in, const int* in_sizes, int n_in,
                              void* d_out, int out_size)
{
    const float* h_l  = (const float*)d_in[0];
    const float* x_l  = (const float*)d_in[1];
    const float* h_r  = (const float*)d_in[2];
    const float* x_r  = (const float*)d_in[3];
    const float* W1   = (const float*)d_in[4];
    const float* b1   = (const float*)d_in[5];
    const float* W2   = (const float*)d_in[6];
    const float* b2   = (const float*)d_in[7];
    const float* Wn1  = (const float*)d_in[8];
    const float* bn1  = (const float*)d_in[9];
    const float* ln_g = (const float*)d_in[10];
    const float* ln_b = (const float*)d_in[11];
    const float* Wn2  = (const float*)d_in[12];
    const float* bn2  = (const float*)d_in[13];
    float* out = (float*)d_out;

    cudaFuncSetAttribute(fused_kernel,
                         cudaFuncAttributeMaxDynamicSharedMemorySize, SMEM_TOTAL);
    fused_kernel<<<GRID, THREADS, SMEM_TOTAL>>>(h_l, x_l, h_r, x_r, W1, b1, W2, b2,
                                                Wn1, bn1, ln_g, ln_b, Wn2, bn2, out);
}